// round 2
// baseline (speedup 1.0000x reference)
#include <cuda_runtime.h>
#include <math_constants.h>

#define BB  4
#define SS  2048
#define DD  1024
#define HH  16
#define DHH 64

// ---------------- scratch (device globals; no allocations) ----------------
__device__ float g_Q[(size_t)BB * HH * SS * DHH];  // (B,H,S,DH)
__device__ float g_K[(size_t)BB * HH * SS * DHH];
__device__ float g_V[(size_t)BB * HH * SS * DHH];
__device__ float g_O[(size_t)BB * SS * DD];        // (B,S,D)

// ---------------- SGEMM core: C(128x64 tile) = A(MxK) @ W(KxN), K=N=1024 ----
// 256 threads, BK=16, microtile 8x4.
__device__ __forceinline__ void sgemm_body(const float* __restrict__ A,
                                           const float* __restrict__ W,
                                           float acc[8][4], int m0, int n0)
{
    __shared__ float As[16][132];  // transposed A tile, padded
    __shared__ float Bs[16][68];   // W tile, padded

    const int tid = threadIdx.x;
    const int ty  = tid >> 4;   // 0..15 -> rows ty*8..+7
    const int tx  = tid & 15;   // 0..15 -> cols tx*4..+3

    for (int k0 = 0; k0 < DD; k0 += 16) {
        // load A tile 128x16 (transposed into As[k][m])
        #pragma unroll
        for (int l = 0; l < 2; l++) {
            int lin = tid + l * 256;
            int row = lin >> 2;
            int cg  = (lin & 3) << 2;
            float4 a = *(const float4*)(A + (size_t)(m0 + row) * DD + k0 + cg);
            As[cg + 0][row] = a.x;
            As[cg + 1][row] = a.y;
            As[cg + 2][row] = a.z;
            As[cg + 3][row] = a.w;
        }
        // load W tile 16x64
        {
            int kk = tid >> 4;
            int nn = (tid & 15) << 2;
            *(float4*)&Bs[kk][nn] =
                *(const float4*)(W + (size_t)(k0 + kk) * DD + n0 + nn);
        }
        __syncthreads();

        #pragma unroll
        for (int kk = 0; kk < 16; kk++) {
            float a[8], b[4];
            #pragma unroll
            for (int i = 0; i < 8; i++) a[i] = As[kk][ty * 8 + i];
            #pragma unroll
            for (int j = 0; j < 4; j++) b[j] = Bs[kk][tx * 4 + j];
            #pragma unroll
            for (int i = 0; i < 8; i++)
                #pragma unroll
                for (int j = 0; j < 4; j++)
                    acc[i][j] += a[i] * b[j];
        }
        __syncthreads();
    }
}

// ---------------- projection GEMMs: Q/K/V via blockIdx.z ----------------
__global__ __launch_bounds__(256) void proj_kernel(
    const float* __restrict__ x,
    const float* __restrict__ Wq, const float* __restrict__ bq,
    const float* __restrict__ Wk, const float* __restrict__ bk,
    const float* __restrict__ Wv, const float* __restrict__ bv)
{
    const int z = blockIdx.z;
    const float* W    = (z == 0) ? Wq : (z == 1) ? Wk : Wv;
    const float* bias = (z == 0) ? bq : (z == 1) ? bk : bv;
    float* out        = (z == 0) ? g_Q : (z == 1) ? g_K : g_V;

    const int m0 = blockIdx.y * 128;
    const int n0 = blockIdx.x * 64;

    float acc[8][4];
    #pragma unroll
    for (int i = 0; i < 8; i++)
        #pragma unroll
        for (int j = 0; j < 4; j++) acc[i][j] = 0.f;

    sgemm_body(x, W, acc, m0, n0);

    const int ty = threadIdx.x >> 4;
    const int tx = threadIdx.x & 15;
    const int h   = n0 >> 6;        // BN==DH==64
    const int dh0 = tx * 4;
    const float4 b4 = *(const float4*)(bias + n0 + tx * 4);

    #pragma unroll
    for (int i = 0; i < 8; i++) {
        int m = m0 + ty * 8 + i;
        int bidx = m >> 11;        // /2048
        int s    = m & 2047;
        float4 r;
        r.x = acc[i][0] + b4.x;
        r.y = acc[i][1] + b4.y;
        r.z = acc[i][2] + b4.z;
        r.w = acc[i][3] + b4.w;
        *(float4*)(out + (((size_t)bidx * HH + h) * SS + s) * DHH + dh0) = r;
    }
}

// ---------------- output projection: d_out = g_O @ Wo + bo ----------------
__global__ __launch_bounds__(256) void outproj_kernel(
    const float* __restrict__ Wo, const float* __restrict__ bo,
    float* __restrict__ out)
{
    const int m0 = blockIdx.y * 128;
    const int n0 = blockIdx.x * 64;

    float acc[8][4];
    #pragma unroll
    for (int i = 0; i < 8; i++)
        #pragma unroll
        for (int j = 0; j < 4; j++) acc[i][j] = 0.f;

    sgemm_body(g_O, Wo, acc, m0, n0);

    const int ty = threadIdx.x >> 4;
    const int tx = threadIdx.x & 15;
    const float4 b4 = *(const float4*)(bo + n0 + tx * 4);

    #pragma unroll
    for (int i = 0; i < 8; i++) {
        int m = m0 + ty * 8 + i;
        float4 r;
        r.x = acc[i][0] + b4.x;
        r.y = acc[i][1] + b4.y;
        r.z = acc[i][2] + b4.z;
        r.w = acc[i][3] + b4.w;
        *(float4*)(out + (size_t)m * DD + n0 + tx * 4) = r;
    }
}

// ---------------- attention: faithful non-normalized flash recurrence -----
// Block = 64 query rows x one (b,h). 256 threads, 4x4 microtiles.
#define ATT_SMEM ((64 * 68 + 64 * 65 + 64 * 64 + 64 * 68) * 4)

__global__ __launch_bounds__(256) void attn_kernel()
{
    extern __shared__ float sm[];
    float* Qs = sm;                  // stride 68
    float* Ks = sm + 64 * 68;        // stride 65 (odd: conflict-light col reads)
    float* Vs = Ks + 64 * 65;        // stride 64 (float4 reads)
    float* Ps = Vs + 64 * 64;        // stride 68

    const int qt = blockIdx.x;
    const int q0 = qt * 64;
    const int bh = blockIdx.y;
    const float* __restrict__ Qg = g_Q + (size_t)bh * SS * DHH;
    const float* __restrict__ Kg = g_K + (size_t)bh * SS * DHH;
    const float* __restrict__ Vg = g_V + (size_t)bh * SS * DHH;

    const int t  = threadIdx.x;
    const int tr = t >> 4;       // 0..15 -> rows tr*4..+3
    const int tc = t & 15;       // 0..15 -> cols tc*4..+3
    const int r0 = tr * 4;
    const int c0 = tc * 4;

    // load Q tile (once)
    #pragma unroll
    for (int l = 0; l < 4; l++) {
        int lin = t + l * 256;
        int row = lin >> 4;
        int cg  = (lin & 15) << 2;
        float4 v = *(const float4*)(Qg + (size_t)(q0 + row) * DHH + cg);
        float* d = Qs + row * 68 + cg;
        d[0] = v.x; d[1] = v.y; d[2] = v.z; d[3] = v.w;
    }

    float O[4][4];
    float mrow[4], lrow[4];
    #pragma unroll
    for (int rr = 0; rr < 4; rr++) {
        mrow[rr] = -CUDART_INF_F;
        lrow[rr] = 0.f;
        #pragma unroll
        for (int cc = 0; cc < 4; cc++) O[rr][cc] = 0.f;
    }

    for (int j = 0; j <= qt; j++) {
        // load K (transposed-read layout, stride 65) and V (natural)
        #pragma unroll
        for (int l = 0; l < 4; l++) {
            int lin = t + l * 256;
            int row = lin >> 4;
            int cg  = (lin & 15) << 2;
            float4 kv = *(const float4*)(Kg + (size_t)(j * 64 + row) * DHH + cg);
            float* dk = Ks + row * 65 + cg;
            dk[0] = kv.x; dk[1] = kv.y; dk[2] = kv.z; dk[3] = kv.w;
            float4 vv = *(const float4*)(Vg + (size_t)(j * 64 + row) * DHH + cg);
            *(float4*)(Vs + row * 64 + cg) = vv;
        }
        __syncthreads();

        // S = Q K^T / 8
        float s[4][4];
        #pragma unroll
        for (int rr = 0; rr < 4; rr++)
            #pragma unroll
            for (int cc = 0; cc < 4; cc++) s[rr][cc] = 0.f;

        const float* qb0 = Qs + (r0 + 0) * 68;
        const float* qb1 = Qs + (r0 + 1) * 68;
        const float* qb2 = Qs + (r0 + 2) * 68;
        const float* qb3 = Qs + (r0 + 3) * 68;
        const float* kb0 = Ks + (c0 + 0) * 65;
        const float* kb1 = Ks + (c0 + 1) * 65;
        const float* kb2 = Ks + (c0 + 2) * 65;
        const float* kb3 = Ks + (c0 + 3) * 65;

        #pragma unroll 8
        for (int k = 0; k < 64; k++) {
            float a0 = qb0[k], a1 = qb1[k], a2 = qb2[k], a3 = qb3[k];
            float b0 = kb0[k], b1 = kb1[k], b2 = kb2[k], b3 = kb3[k];
            s[0][0] += a0 * b0; s[0][1] += a0 * b1; s[0][2] += a0 * b2; s[0][3] += a0 * b3;
            s[1][0] += a1 * b0; s[1][1] += a1 * b1; s[1][2] += a1 * b2; s[1][3] += a1 * b3;
            s[2][0] += a2 * b0; s[2][1] += a2 * b1; s[2][2] += a2 * b2; s[2][3] += a2 * b3;
            s[3][0] += a3 * b0; s[3][1] += a3 * b1; s[3][2] += a3 * b2; s[3][3] += a3 * b3;
        }

        const bool diag = (j == qt);
        #pragma unroll
        for (int rr = 0; rr < 4; rr++) {
            const int q = q0 + r0 + rr;
            float mx = -CUDART_INF_F;
            #pragma unroll
            for (int cc = 0; cc < 4; cc++) {
                float val = s[rr][cc] * 0.125f;
                if (diag && (j * 64 + c0 + cc > q)) val = -CUDART_INF_F;
                s[rr][cc] = val;
                mx = fmaxf(mx, val);
            }
            // row reductions across the 16 lanes sharing tr (lanes are 16-aligned)
            mx = fmaxf(mx, __shfl_xor_sync(0xffffffffu, mx, 1));
            mx = fmaxf(mx, __shfl_xor_sync(0xffffffffu, mx, 2));
            mx = fmaxf(mx, __shfl_xor_sync(0xffffffffu, mx, 4));
            mx = fmaxf(mx, __shfl_xor_sync(0xffffffffu, mx, 8));

            const float mnew = fmaxf(mrow[rr], mx);
            float lsum = 0.f;
            #pragma unroll
            for (int cc = 0; cc < 4; cc++) {
                float p = __expf(s[rr][cc] - mnew);   // exp(-inf)=0 handles mask
                s[rr][cc] = p;
                lsum += p;
            }
            lsum += __shfl_xor_sync(0xffffffffu, lsum, 1);
            lsum += __shfl_xor_sync(0xffffffffu, lsum, 2);
            lsum += __shfl_xor_sync(0xffffffffu, lsum, 4);
            lsum += __shfl_xor_sync(0xffffffffu, lsum, 8);

            const float alpha = __expf(mrow[rr] - mnew);       // exp(-inf)=0 first iter
            const float lnew  = alpha * lrow[rr] + lsum;       // > 0 always
            const float f     = lrow[rr] / lnew * alpha;       // exact reference recurrence
            #pragma unroll
            for (int cc = 0; cc < 4; cc++) O[rr][cc] *= f;
            mrow[rr] = mnew;
            lrow[rr] = lnew;

            float* pd = Ps + (r0 + rr) * 68 + c0;
            pd[0] = s[rr][0]; pd[1] = s[rr][1]; pd[2] = s[rr][2]; pd[3] = s[rr][3];
        }
        __syncthreads();

        // O += P @ V
        const float* pb0 = Ps + (r0 + 0) * 68;
        const float* pb1 = Ps + (r0 + 1) * 68;
        const float* pb2 = Ps + (r0 + 2) * 68;
        const float* pb3 = Ps + (r0 + 3) * 68;
        #pragma unroll 4
        for (int kk = 0; kk < 64; kk++) {
            float p0 = pb0[kk], p1 = pb1[kk], p2 = pb2[kk], p3 = pb3[kk];
            float4 v4 = *(const float4*)(Vs + kk * 64 + c0);
            O[0][0] += p0 * v4.x; O[0][1] += p0 * v4.y; O[0][2] += p0 * v4.z; O[0][3] += p0 * v4.w;
            O[1][0] += p1 * v4.x; O[1][1] += p1 * v4.y; O[1][2] += p1 * v4.z; O[1][3] += p1 * v4.w;
            O[2][0] += p2 * v4.x; O[2][1] += p2 * v4.y; O[2][2] += p2 * v4.z; O[2][3] += p2 * v4.w;
            O[3][0] += p3 * v4.x; O[3][1] += p3 * v4.y; O[3][2] += p3 * v4.z; O[3][3] += p3 * v4.w;
        }
        __syncthreads();
    }

    // write O in (B,S,D) layout for the output projection
    const int b = bh >> 4;
    const int h = bh & 15;
    #pragma unroll
    for (int rr = 0; rr < 4; rr++) {
        const int q = q0 + r0 + rr;
        float4 o4;
        o4.x = O[rr][0]; o4.y = O[rr][1]; o4.z = O[rr][2]; o4.w = O[rr][3];
        *(float4*)(g_O + ((size_t)b * SS + q) * DD + h * DHH + c0) = o4;
    }
}

// ---------------- launch ----------------
extern "C" void kernel_launch(void* const* d_in, const int* in_sizes, int n_in,
                              void* d_out, int out_size)
{
    const float* x  = (const float*)d_in[0];
    const float* Wq = (const float*)d_in[1];
    const float* bq = (const float*)d_in[2];
    const float* Wk = (const float*)d_in[3];
    const float* bk = (const float*)d_in[4];
    const float* Wv = (const float*)d_in[5];
    const float* bv = (const float*)d_in[6];
    const float* Wo = (const float*)d_in[7];
    const float* bo = (const float*)d_in[8];
    float* out = (float*)d_out;

    static bool attr_done = false;
    if (!attr_done) {
        cudaFuncSetAttribute(attn_kernel,
                             cudaFuncAttributeMaxDynamicSharedMemorySize, ATT_SMEM);
        attr_done = true;
    }

    proj_kernel<<<dim3(DD / 64, (BB * SS) / 128, 3), 256>>>(x, Wq, bq, Wk, bk, Wv, bv);
    attn_kernel<<<dim3(SS / 64, BB * HH), 256, ATT_SMEM>>>();
    outproj_kernel<<<dim3(DD / 64, (BB * SS) / 128), 256>>>(Wo, bo, out);
}

// round 6
// speedup vs baseline: 1.4707x; 1.4707x over previous
#include <cuda_runtime.h>
#include <cuda_bf16.h>
#include <math_constants.h>
#include <cstdint>

#define BB  4
#define SS  2048
#define DD  1024
#define HH  16
#define DHH 64

// ---------------- scratch (device globals; no allocations) ----------------
__device__ __nv_bfloat16 g_xh[(size_t)BB * SS * DD];
__device__ __nv_bfloat16 g_xl[(size_t)BB * SS * DD];
__device__ __nv_bfloat16 g_WqTh[(size_t)DD * DD], g_WqTl[(size_t)DD * DD];
__device__ __nv_bfloat16 g_WkTh[(size_t)DD * DD], g_WkTl[(size_t)DD * DD];
__device__ __nv_bfloat16 g_WvTh[(size_t)DD * DD], g_WvTl[(size_t)DD * DD];
__device__ __nv_bfloat16 g_WoTh[(size_t)DD * DD], g_WoTl[(size_t)DD * DD];
__device__ float g_Q[(size_t)BB * HH * SS * DHH];  // (B,H,S,DH)
__device__ float g_K[(size_t)BB * HH * SS * DHH];
__device__ float g_V[(size_t)BB * HH * SS * DHH];
__device__ __nv_bfloat16 g_Oh[(size_t)BB * SS * DD];  // attention out, (B,S,D)
__device__ __nv_bfloat16 g_Ol[(size_t)BB * SS * DD];

// ---------------- PTX helpers (sm_80+ only: ldmatrix + mma.sync) ----------
__device__ __forceinline__ uint32_t s2u(const void* p) {
    uint32_t a;
    asm("{ .reg .u64 t; cvta.to.shared.u64 t, %1; cvt.u32.u64 %0, t; }"
        : "=r"(a) : "l"(p));
    return a;
}

__device__ __forceinline__ void ldsm4(uint32_t* r, uint32_t addr) {
    asm volatile("ldmatrix.sync.aligned.m8n8.x4.shared.b16 {%0,%1,%2,%3}, [%4];"
        : "=r"(r[0]), "=r"(r[1]), "=r"(r[2]), "=r"(r[3]) : "r"(addr));
}
__device__ __forceinline__ void ldsm2(uint32_t* r, uint32_t addr) {
    asm volatile("ldmatrix.sync.aligned.m8n8.x2.shared.b16 {%0,%1}, [%2];"
        : "=r"(r[0]), "=r"(r[1]) : "r"(addr));
}
__device__ __forceinline__ void mma_bf16(float* d, const uint32_t* a, const uint32_t* b) {
    asm volatile(
        "mma.sync.aligned.m16n8k16.row.col.f32.bf16.bf16.f32 "
        "{%0,%1,%2,%3}, {%4,%5,%6,%7}, {%8,%9}, {%0,%1,%2,%3};"
        : "+f"(d[0]), "+f"(d[1]), "+f"(d[2]), "+f"(d[3])
        : "r"(a[0]), "r"(a[1]), "r"(a[2]), "r"(a[3]), "r"(b[0]), "r"(b[1]));
}

// ---------------- bf16 hi/lo split kernels ----------------
__global__ __launch_bounds__(256) void split_x(const float* __restrict__ x) {
    size_t i = ((size_t)blockIdx.x * 256 + threadIdx.x) * 4;
    float4 v = *(const float4*)(x + i);
    float vv[4] = {v.x, v.y, v.z, v.w};
    __nv_bfloat16 h[4], l[4];
    #pragma unroll
    for (int j = 0; j < 4; j++) {
        h[j] = __float2bfloat16(vv[j]);
        l[j] = __float2bfloat16(vv[j] - __bfloat162float(h[j]));
    }
    *(uint2*)(g_xh + i) = *(uint2*)h;
    *(uint2*)(g_xl + i) = *(uint2*)l;
}

// transpose W (K,N)->(N,K) + split into bf16 hi/lo
__global__ void transpose_split(const float* __restrict__ Wq, const float* __restrict__ Wk,
                                const float* __restrict__ Wv, const float* __restrict__ Wo) {
    __shared__ float t[32][33];
    const int z = blockIdx.z;
    const float* W = (z == 0) ? Wq : (z == 1) ? Wk : (z == 2) ? Wv : Wo;
    __nv_bfloat16* Th = (z == 0) ? g_WqTh : (z == 1) ? g_WkTh : (z == 2) ? g_WvTh : g_WoTh;
    __nv_bfloat16* Tl = (z == 0) ? g_WqTl : (z == 1) ? g_WkTl : (z == 2) ? g_WvTl : g_WoTl;
    const int n0 = blockIdx.x * 32, k0 = blockIdx.y * 32;
    const int tx = threadIdx.x, ty = threadIdx.y;
    #pragma unroll
    for (int j = 0; j < 32; j += 8)
        t[ty + j][tx] = W[(size_t)(k0 + ty + j) * DD + n0 + tx];
    __syncthreads();
    #pragma unroll
    for (int j = 0; j < 32; j += 8) {
        float v = t[tx][ty + j];
        int n = n0 + ty + j, k = k0 + tx;
        __nv_bfloat16 h = __float2bfloat16(v);
        __nv_bfloat16 l = __float2bfloat16(v - __bfloat162float(h));
        Th[(size_t)n * DD + k] = h;
        Tl[(size_t)n * DD + k] = l;
    }
}

// ---------------- mma.sync GEMM: 128x128 tile, bf16x3, K=1024 --------------
// 8 warps in 2(M) x 4(N); warp tile 64x32; K-chunk 32, double-buffered smem.
// Smem row stride: 40 bf16 = 80 B (5 x 16B -> conflict-free ldmatrix).
#define KCH     32
#define NCHUNK  (DD / KCH)          // 32
#define RSTR    40                  // bf16 units per smem row
#define TILE_B  (128 * RSTR * 2)    // 10240 B, one 128x32 bf16 tile
#define OFF_AH  0
#define OFF_AL  (TILE_B)
#define OFF_BH  (2 * TILE_B)
#define OFF_BL  (3 * TILE_B)
#define BUF_B   (4 * TILE_B)        // 40960 B per buffer
#define GEMM_SMEM (2 * BUF_B)       // 81920 B

struct LdgRegs { uint4 ah[2], al[2], bh[2], bl[2]; };

__device__ __forceinline__ void ldg_chunk(
    const __nv_bfloat16* __restrict__ Ah, const __nv_bfloat16* __restrict__ Al,
    const __nv_bfloat16* __restrict__ Bh, const __nv_bfloat16* __restrict__ Bl,
    int m0, int n0, int k0, int tid, LdgRegs& r)
{
    #pragma unroll
    for (int it = 0; it < 2; it++) {
        int gid = tid + it * 256;
        int row = gid >> 2, kg = (gid & 3) << 3;
        r.ah[it] = *(const uint4*)(Ah + (size_t)(m0 + row) * DD + k0 + kg);
        r.al[it] = *(const uint4*)(Al + (size_t)(m0 + row) * DD + k0 + kg);
        r.bh[it] = *(const uint4*)(Bh + (size_t)(n0 + row) * DD + k0 + kg);
        r.bl[it] = *(const uint4*)(Bl + (size_t)(n0 + row) * DD + k0 + kg);
    }
}

__device__ __forceinline__ void sts_chunk(char* buf, int tid, const LdgRegs& r)
{
    #pragma unroll
    for (int it = 0; it < 2; it++) {
        int gid = tid + it * 256;
        int row = gid >> 2, kg = (gid & 3) << 3;
        uint32_t off = (uint32_t)(row * RSTR + kg) * 2;
        *(uint4*)(buf + OFF_AH + off) = r.ah[it];
        *(uint4*)(buf + OFF_AL + off) = r.al[it];
        *(uint4*)(buf + OFF_BH + off) = r.bh[it];
        *(uint4*)(buf + OFF_BL + off) = r.bl[it];
    }
}

// full mainloop: acc[mi][ni][4] = (A row-block m0) @ (B^T n-block n0)
__device__ __forceinline__ void gemm_loop(
    const __nv_bfloat16* __restrict__ Ah, const __nv_bfloat16* __restrict__ Al,
    const __nv_bfloat16* __restrict__ Bh, const __nv_bfloat16* __restrict__ Bl,
    int m0, int n0, char* sm, float acc[4][4][4])
{
    const int tid  = threadIdx.x;
    const int lane = tid & 31;
    const int warp = tid >> 5;
    const int wm   = warp & 1;      // 0/1 -> M halves of 64
    const int wn   = warp >> 1;     // 0..3 -> N quarters of 32

    const uint32_t sb = s2u(sm);
    // ldmatrix per-lane row/k offsets
    const int a_row = wm * 64 + (lane & 7) + ((lane >> 3) & 1) * 8;
    const int a_kof = (lane >> 4) * 8;
    const int b_row = wn * 32 + (lane & 7);
    const int b_kof = ((lane >> 3) & 1) * 8;

    LdgRegs r;
    ldg_chunk(Ah, Al, Bh, Bl, m0, n0, 0, tid, r);
    sts_chunk(sm, tid, r);
    __syncthreads();

    for (int c = 0; c < NCHUNK; c++) {
        if (c + 1 < NCHUNK)
            ldg_chunk(Ah, Al, Bh, Bl, m0, n0, (c + 1) * KCH, tid, r);

        const uint32_t bufb = sb + (uint32_t)(c & 1) * BUF_B;
        #pragma unroll
        for (int ks = 0; ks < 2; ks++) {
            uint32_t fah[4][4], fal[4][4], fbh[4][2], fbl[4][2];
            #pragma unroll
            for (int mi = 0; mi < 4; mi++) {
                uint32_t ao = bufb + (uint32_t)(((a_row + mi * 16) * RSTR) + ks * 16 + a_kof) * 2;
                ldsm4(fah[mi], ao + OFF_AH);
                ldsm4(fal[mi], ao + OFF_AL);
            }
            #pragma unroll
            for (int ni = 0; ni < 4; ni++) {
                uint32_t bo = bufb + (uint32_t)(((b_row + ni * 8) * RSTR) + ks * 16 + b_kof) * 2;
                ldsm2(fbh[ni], bo + OFF_BH);
                ldsm2(fbl[ni], bo + OFF_BL);
            }
            #pragma unroll
            for (int mi = 0; mi < 4; mi++)
                #pragma unroll
                for (int ni = 0; ni < 4; ni++) {
                    mma_bf16(acc[mi][ni], fah[mi], fbh[ni]);
                    mma_bf16(acc[mi][ni], fah[mi], fbl[ni]);
                    mma_bf16(acc[mi][ni], fal[mi], fbh[ni]);
                }
        }

        if (c + 1 < NCHUNK) {
            sts_chunk(sm + ((c + 1) & 1) * BUF_B, tid, r);
            __syncthreads();
        }
    }
}

// ---------------- projection GEMMs (Q/K/V) ----------------
__global__ __launch_bounds__(256, 1) void proj_tc(const float* __restrict__ bq,
                                                  const float* __restrict__ bk,
                                                  const float* __restrict__ bv)
{
    extern __shared__ char sm[];
    const int z = blockIdx.z;
    const __nv_bfloat16* Bh = (z == 0) ? g_WqTh : (z == 1) ? g_WkTh : g_WvTh;
    const __nv_bfloat16* Bl = (z == 0) ? g_WqTl : (z == 1) ? g_WkTl : g_WvTl;
    const float* bias       = (z == 0) ? bq : (z == 1) ? bk : bv;
    float* out              = (z == 0) ? g_Q : (z == 1) ? g_K : g_V;

    const int m0 = blockIdx.y * 128;
    const int n0 = blockIdx.x * 128;

    float acc[4][4][4];
    #pragma unroll
    for (int mi = 0; mi < 4; mi++)
        #pragma unroll
        for (int ni = 0; ni < 4; ni++)
            #pragma unroll
            for (int k = 0; k < 4; k++) acc[mi][ni][k] = 0.f;

    gemm_loop(g_xh, g_xl, Bh, Bl, m0, n0, sm, acc);

    const int lane = threadIdx.x & 31;
    const int warp = threadIdx.x >> 5;
    const int wm = warp & 1, wn = warp >> 1;

    #pragma unroll
    for (int ni = 0; ni < 4; ni++) {
        const int gn = n0 + wn * 32 + ni * 8 + (lane & 3) * 2;
        const int h = gn >> 6, dh = gn & 63;
        const float b0 = bias[gn], b1 = bias[gn + 1];
        #pragma unroll
        for (int mi = 0; mi < 4; mi++) {
            const int gm = m0 + wm * 64 + mi * 16 + (lane >> 2);
            #pragma unroll
            for (int rh = 0; rh < 2; rh++) {
                const int m = gm + rh * 8;
                const int bidx = m >> 11, s = m & 2047;
                float2 v;
                v.x = acc[mi][ni][rh * 2 + 0] + b0;
                v.y = acc[mi][ni][rh * 2 + 1] + b1;
                *(float2*)(out + (((size_t)bidx * HH + h) * SS + s) * DHH + dh) = v;
            }
        }
    }
}

// ---------------- output projection ----------------
__global__ __launch_bounds__(256, 1) void outproj_tc(const float* __restrict__ bo,
                                                     float* __restrict__ out)
{
    extern __shared__ char sm[];
    const int m0 = blockIdx.y * 128;
    const int n0 = blockIdx.x * 128;

    float acc[4][4][4];
    #pragma unroll
    for (int mi = 0; mi < 4; mi++)
        #pragma unroll
        for (int ni = 0; ni < 4; ni++)
            #pragma unroll
            for (int k = 0; k < 4; k++) acc[mi][ni][k] = 0.f;

    gemm_loop(g_Oh, g_Ol, g_WoTh, g_WoTl, m0, n0, sm, acc);

    const int lane = threadIdx.x & 31;
    const int warp = threadIdx.x >> 5;
    const int wm = warp & 1, wn = warp >> 1;

    #pragma unroll
    for (int ni = 0; ni < 4; ni++) {
        const int gn = n0 + wn * 32 + ni * 8 + (lane & 3) * 2;
        const float b0 = bo[gn], b1 = bo[gn + 1];
        #pragma unroll
        for (int mi = 0; mi < 4; mi++) {
            const int gm = m0 + wm * 64 + mi * 16 + (lane >> 2);
            #pragma unroll
            for (int rh = 0; rh < 2; rh++) {
                const int m = gm + rh * 8;
                float2 v;
                v.x = acc[mi][ni][rh * 2 + 0] + b0;
                v.y = acc[mi][ni][rh * 2 + 1] + b1;
                *(float2*)(out + (size_t)m * DD + gn) = v;
            }
        }
    }
}

// ---------------- attention: faithful non-normalized flash recurrence -----
#define ATT_SMEM ((64 * 68 + 64 * 65 + 64 * 64 + 64 * 68) * 4)

__global__ __launch_bounds__(256) void attn_kernel()
{
    extern __shared__ float smf[];
    float* Qs = smf;
    float* Ks = smf + 64 * 68;
    float* Vs = Ks + 64 * 65;
    float* Ps = Vs + 64 * 64;

    const int qt = blockIdx.x;
    const int q0 = qt * 64;
    const int bh = blockIdx.y;
    const float* __restrict__ Qg = g_Q + (size_t)bh * SS * DHH;
    const float* __restrict__ Kg = g_K + (size_t)bh * SS * DHH;
    const float* __restrict__ Vg = g_V + (size_t)bh * SS * DHH;

    const int t  = threadIdx.x;
    const int tr = t >> 4;
    const int tc = t & 15;
    const int r0 = tr * 4;
    const int c0 = tc * 4;

    #pragma unroll
    for (int l = 0; l < 4; l++) {
        int lin = t + l * 256;
        int row = lin >> 4;
        int cg  = (lin & 15) << 2;
        float4 v = *(const float4*)(Qg + (size_t)(q0 + row) * DHH + cg);
        float* d = Qs + row * 68 + cg;
        d[0] = v.x; d[1] = v.y; d[2] = v.z; d[3] = v.w;
    }

    float O[4][4];
    float mrow[4], lrow[4];
    #pragma unroll
    for (int rr = 0; rr < 4; rr++) {
        mrow[rr] = -CUDART_INF_F;
        lrow[rr] = 0.f;
        #pragma unroll
        for (int cc = 0; cc < 4; cc++) O[rr][cc] = 0.f;
    }

    for (int j = 0; j <= qt; j++) {
        #pragma unroll
        for (int l = 0; l < 4; l++) {
            int lin = t + l * 256;
            int row = lin >> 4;
            int cg  = (lin & 15) << 2;
            float4 kv = *(const float4*)(Kg + (size_t)(j * 64 + row) * DHH + cg);
            float* dk = Ks + row * 65 + cg;
            dk[0] = kv.x; dk[1] = kv.y; dk[2] = kv.z; dk[3] = kv.w;
            float4 vv = *(const float4*)(Vg + (size_t)(j * 64 + row) * DHH + cg);
            *(float4*)(Vs + row * 64 + cg) = vv;
        }
        __syncthreads();

        float s[4][4];
        #pragma unroll
        for (int rr = 0; rr < 4; rr++)
            #pragma unroll
            for (int cc = 0; cc < 4; cc++) s[rr][cc] = 0.f;

        const float* qb0 = Qs + (r0 + 0) * 68;
        const float* qb1 = Qs + (r0 + 1) * 68;
        const float* qb2 = Qs + (r0 + 2) * 68;
        const float* qb3 = Qs + (r0 + 3) * 68;
        const float* kb0 = Ks + (c0 + 0) * 65;
        const float* kb1 = Ks + (c0 + 1) * 65;
        const float* kb2 = Ks + (c0 + 2) * 65;
        const float* kb3 = Ks + (c0 + 3) * 65;

        #pragma unroll 8
        for (int k = 0; k < 64; k++) {
            float a0 = qb0[k], a1 = qb1[k], a2 = qb2[k], a3 = qb3[k];
            float b0 = kb0[k], b1 = kb1[k], b2 = kb2[k], b3 = kb3[k];
            s[0][0] += a0 * b0; s[0][1] += a0 * b1; s[0][2] += a0 * b2; s[0][3] += a0 * b3;
            s[1][0] += a1 * b0; s[1][1] += a1 * b1; s[1][2] += a1 * b2; s[1][3] += a1 * b3;
            s[2][0] += a2 * b0; s[2][1] += a2 * b1; s[2][2] += a2 * b2; s[2][3] += a2 * b3;
            s[3][0] += a3 * b0; s[3][1] += a3 * b1; s[3][2] += a3 * b2; s[3][3] += a3 * b3;
        }

        const bool diag = (j == qt);
        #pragma unroll
        for (int rr = 0; rr < 4; rr++) {
            const int q = q0 + r0 + rr;
            float mx = -CUDART_INF_F;
            #pragma unroll
            for (int cc = 0; cc < 4; cc++) {
                float val = s[rr][cc] * 0.125f;
                if (diag && (j * 64 + c0 + cc > q)) val = -CUDART_INF_F;
                s[rr][cc] = val;
                mx = fmaxf(mx, val);
            }
            mx = fmaxf(mx, __shfl_xor_sync(0xffffffffu, mx, 1));
            mx = fmaxf(mx, __shfl_xor_sync(0xffffffffu, mx, 2));
            mx = fmaxf(mx, __shfl_xor_sync(0xffffffffu, mx, 4));
            mx = fmaxf(mx, __shfl_xor_sync(0xffffffffu, mx, 8));

            const float mnew = fmaxf(mrow[rr], mx);
            float lsum = 0.f;
            #pragma unroll
            for (int cc = 0; cc < 4; cc++) {
                float p = __expf(s[rr][cc] - mnew);
                s[rr][cc] = p;
                lsum += p;
            }
            lsum += __shfl_xor_sync(0xffffffffu, lsum, 1);
            lsum += __shfl_xor_sync(0xffffffffu, lsum, 2);
            lsum += __shfl_xor_sync(0xffffffffu, lsum, 4);
            lsum += __shfl_xor_sync(0xffffffffu, lsum, 8);

            const float alpha = __expf(mrow[rr] - mnew);
            const float lnew  = alpha * lrow[rr] + lsum;
            const float f     = lrow[rr] / lnew * alpha;
            #pragma unroll
            for (int cc = 0; cc < 4; cc++) O[rr][cc] *= f;
            mrow[rr] = mnew;
            lrow[rr] = lnew;

            float* pd = Ps + (r0 + rr) * 68 + c0;
            pd[0] = s[rr][0]; pd[1] = s[rr][1]; pd[2] = s[rr][2]; pd[3] = s[rr][3];
        }
        __syncthreads();

        const float* pb0 = Ps + (r0 + 0) * 68;
        const float* pb1 = Ps + (r0 + 1) * 68;
        const float* pb2 = Ps + (r0 + 2) * 68;
        const float* pb3 = Ps + (r0 + 3) * 68;
        #pragma unroll 4
        for (int kk = 0; kk < 64; kk++) {
            float p0 = pb0[kk], p1 = pb1[kk], p2 = pb2[kk], p3 = pb3[kk];
            float4 v4 = *(const float4*)(Vs + kk * 64 + c0);
            O[0][0] += p0 * v4.x; O[0][1] += p0 * v4.y; O[0][2] += p0 * v4.z; O[0][3] += p0 * v4.w;
            O[1][0] += p1 * v4.x; O[1][1] += p1 * v4.y; O[1][2] += p1 * v4.z; O[1][3] += p1 * v4.w;
            O[2][0] += p2 * v4.x; O[2][1] += p2 * v4.y; O[2][2] += p2 * v4.z; O[2][3] += p2 * v4.w;
            O[3][0] += p3 * v4.x; O[3][1] += p3 * v4.y; O[3][2] += p3 * v4.z; O[3][3] += p3 * v4.w;
        }
        __syncthreads();
    }

    // write O as bf16 hi/lo in (B,S,D) layout for the tensor-core out-proj
    const int b = bh >> 4;
    const int h = bh & 15;
    #pragma unroll
    for (int rr = 0; rr < 4; rr++) {
        const int q = q0 + r0 + rr;
        const size_t base = ((size_t)b * SS + q) * DD + h * DHH + c0;
        __nv_bfloat16 hv[4], lv[4];
        #pragma unroll
        for (int cc = 0; cc < 4; cc++) {
            float o = O[rr][cc];
            hv[cc] = __float2bfloat16(o);
            lv[cc] = __float2bfloat16(o - __bfloat162float(hv[cc]));
        }
        *(uint2*)(g_Oh + base) = *(uint2*)hv;
        *(uint2*)(g_Ol + base) = *(uint2*)lv;
    }
}

// ---------------- launch ----------------
extern "C" void kernel_launch(void* const* d_in, const int* in_sizes, int n_in,
                              void* d_out, int out_size)
{
    const float* x  = (const float*)d_in[0];
    const float* Wq = (const float*)d_in[1];
    const float* bq = (const float*)d_in[2];
    const float* Wk = (const float*)d_in[3];
    const float* bk = (const float*)d_in[4];
    const float* Wv = (const float*)d_in[5];
    const float* bv = (const float*)d_in[6];
    const float* Wo = (const float*)d_in[7];
    const float* bo = (const float*)d_in[8];
    float* out = (float*)d_out;

    static bool attr_done = false;
    if (!attr_done) {
        cudaFuncSetAttribute(attn_kernel,
                             cudaFuncAttributeMaxDynamicSharedMemorySize, ATT_SMEM);
        cudaFuncSetAttribute(proj_tc,
                             cudaFuncAttributeMaxDynamicSharedMemorySize, GEMM_SMEM);
        cudaFuncSetAttribute(outproj_tc,
                             cudaFuncAttributeMaxDynamicSharedMemorySize, GEMM_SMEM);
        attr_done = true;
    }

    split_x<<<(BB * SS * DD) / (256 * 4), 256>>>(x);
    transpose_split<<<dim3(DD / 32, DD / 32, 4), dim3(32, 8)>>>(Wq, Wk, Wv, Wo);
    proj_tc<<<dim3(DD / 128, (BB * SS) / 128, 3), 256, GEMM_SMEM>>>(bq, bk, bv);
    attn_kernel<<<dim3(SS / 64, BB * HH), 256, ATT_SMEM>>>();
    outproj_tc<<<dim3(DD / 128, (BB * SS) / 128), 256, GEMM_SMEM>>>(bo, out);
}

// round 7
// speedup vs baseline: 2.5833x; 1.7565x over previous
#include <cuda_runtime.h>
#include <cuda_bf16.h>
#include <math_constants.h>
#include <cstdint>

#define BB  4
#define SS  2048
#define DD  1024
#define HH  16
#define DHH 64

// ---------------- scratch (device globals; no allocations) ----------------
__device__ __nv_bfloat16 g_xh[(size_t)BB * SS * DD];
__device__ __nv_bfloat16 g_xl[(size_t)BB * SS * DD];
__device__ __nv_bfloat16 g_WqTh[(size_t)DD * DD], g_WqTl[(size_t)DD * DD];
__device__ __nv_bfloat16 g_WkTh[(size_t)DD * DD], g_WkTl[(size_t)DD * DD];
__device__ __nv_bfloat16 g_WvTh[(size_t)DD * DD], g_WvTl[(size_t)DD * DD];
__device__ __nv_bfloat16 g_WoTh[(size_t)DD * DD], g_WoTl[(size_t)DD * DD];
// Q/K/V as bf16 hi/lo, (B,H,S,DH)
__device__ __nv_bfloat16 g_Qh[(size_t)BB * HH * SS * DHH], g_Ql[(size_t)BB * HH * SS * DHH];
__device__ __nv_bfloat16 g_Kh[(size_t)BB * HH * SS * DHH], g_Kl[(size_t)BB * HH * SS * DHH];
__device__ __nv_bfloat16 g_Vh[(size_t)BB * HH * SS * DHH], g_Vl[(size_t)BB * HH * SS * DHH];
__device__ __nv_bfloat16 g_Oh[(size_t)BB * SS * DD];  // attention out, (B,S,D)
__device__ __nv_bfloat16 g_Ol[(size_t)BB * SS * DD];

// ---------------- PTX helpers (sm_80+ only) ----------------
__device__ __forceinline__ uint32_t s2u(const void* p) {
    uint32_t a;
    asm("{ .reg .u64 t; cvta.to.shared.u64 t, %1; cvt.u32.u64 %0, t; }"
        : "=r"(a) : "l"(p));
    return a;
}
__device__ __forceinline__ void ldsm4(uint32_t* r, uint32_t addr) {
    asm volatile("ldmatrix.sync.aligned.m8n8.x4.shared.b16 {%0,%1,%2,%3}, [%4];"
        : "=r"(r[0]), "=r"(r[1]), "=r"(r[2]), "=r"(r[3]) : "r"(addr));
}
__device__ __forceinline__ void ldsm4t(uint32_t* r, uint32_t addr) {
    asm volatile("ldmatrix.sync.aligned.m8n8.x4.trans.shared.b16 {%0,%1,%2,%3}, [%4];"
        : "=r"(r[0]), "=r"(r[1]), "=r"(r[2]), "=r"(r[3]) : "r"(addr));
}
__device__ __forceinline__ void ldsm2(uint32_t* r, uint32_t addr) {
    asm volatile("ldmatrix.sync.aligned.m8n8.x2.shared.b16 {%0,%1}, [%2];"
        : "=r"(r[0]), "=r"(r[1]) : "r"(addr));
}
__device__ __forceinline__ void mma_bf16(float* d, const uint32_t* a, const uint32_t* b) {
    asm volatile(
        "mma.sync.aligned.m16n8k16.row.col.f32.bf16.bf16.f32 "
        "{%0,%1,%2,%3}, {%4,%5,%6,%7}, {%8,%9}, {%0,%1,%2,%3};"
        : "+f"(d[0]), "+f"(d[1]), "+f"(d[2]), "+f"(d[3])
        : "r"(a[0]), "r"(a[1]), "r"(a[2]), "r"(a[3]), "r"(b[0]), "r"(b[1]));
}
__device__ __forceinline__ void cpa16(uint32_t s, const void* g) {
    asm volatile("cp.async.cg.shared.global [%0], [%1], 16;" :: "r"(s), "l"(g));
}
#define CPA_COMMIT() asm volatile("cp.async.commit_group;" ::: "memory")
#define CPA_WAIT(n)  asm volatile("cp.async.wait_group %0;" :: "n"(n) : "memory")

__device__ __forceinline__ uint32_t packbf(float x, float y) {
    __nv_bfloat162 t = __floats2bfloat162_rn(x, y);
    return *(uint32_t*)&t;
}
__device__ __forceinline__ void split2(float a, float b, uint32_t& h, uint32_t& l) {
    float ha = __bfloat162float(__float2bfloat16(a));
    float hb = __bfloat162float(__float2bfloat16(b));
    h = packbf(ha, hb);
    l = packbf(a - ha, b - hb);
}

// ---------------- bf16 hi/lo split kernels ----------------
__global__ __launch_bounds__(256) void split_x(const float* __restrict__ x) {
    size_t i = ((size_t)blockIdx.x * 256 + threadIdx.x) * 4;
    float4 v = *(const float4*)(x + i);
    float vv[4] = {v.x, v.y, v.z, v.w};
    __nv_bfloat16 h[4], l[4];
    #pragma unroll
    for (int j = 0; j < 4; j++) {
        h[j] = __float2bfloat16(vv[j]);
        l[j] = __float2bfloat16(vv[j] - __bfloat162float(h[j]));
    }
    *(uint2*)(g_xh + i) = *(uint2*)h;
    *(uint2*)(g_xl + i) = *(uint2*)l;
}

__global__ void transpose_split(const float* __restrict__ Wq, const float* __restrict__ Wk,
                                const float* __restrict__ Wv, const float* __restrict__ Wo) {
    __shared__ float t[32][33];
    const int z = blockIdx.z;
    const float* W = (z == 0) ? Wq : (z == 1) ? Wk : (z == 2) ? Wv : Wo;
    __nv_bfloat16* Th = (z == 0) ? g_WqTh : (z == 1) ? g_WkTh : (z == 2) ? g_WvTh : g_WoTh;
    __nv_bfloat16* Tl = (z == 0) ? g_WqTl : (z == 1) ? g_WkTl : (z == 2) ? g_WvTl : g_WoTl;
    const int n0 = blockIdx.x * 32, k0 = blockIdx.y * 32;
    const int tx = threadIdx.x, ty = threadIdx.y;
    #pragma unroll
    for (int j = 0; j < 32; j += 8)
        t[ty + j][tx] = W[(size_t)(k0 + ty + j) * DD + n0 + tx];
    __syncthreads();
    #pragma unroll
    for (int j = 0; j < 32; j += 8) {
        float v = t[tx][ty + j];
        int n = n0 + ty + j, k = k0 + tx;
        __nv_bfloat16 h = __float2bfloat16(v);
        __nv_bfloat16 l = __float2bfloat16(v - __bfloat162float(h));
        Th[(size_t)n * DD + k] = h;
        Tl[(size_t)n * DD + k] = l;
    }
}

// ---------------- mma.sync GEMM: 128x128 tile, bf16x3, K=1024 --------------
#define KCH     32
#define NCHUNK  (DD / KCH)
#define RSTR    40
#define TILE_B  (128 * RSTR * 2)
#define OFF_AH  0
#define OFF_AL  (TILE_B)
#define OFF_BH  (2 * TILE_B)
#define OFF_BL  (3 * TILE_B)
#define BUF_B   (4 * TILE_B)
#define GEMM_SMEM (2 * BUF_B)

struct LdgRegs { uint4 ah[2], al[2], bh[2], bl[2]; };

__device__ __forceinline__ void ldg_chunk(
    const __nv_bfloat16* __restrict__ Ah, const __nv_bfloat16* __restrict__ Al,
    const __nv_bfloat16* __restrict__ Bh, const __nv_bfloat16* __restrict__ Bl,
    int m0, int n0, int k0, int tid, LdgRegs& r)
{
    #pragma unroll
    for (int it = 0; it < 2; it++) {
        int gid = tid + it * 256;
        int row = gid >> 2, kg = (gid & 3) << 3;
        r.ah[it] = *(const uint4*)(Ah + (size_t)(m0 + row) * DD + k0 + kg);
        r.al[it] = *(const uint4*)(Al + (size_t)(m0 + row) * DD + k0 + kg);
        r.bh[it] = *(const uint4*)(Bh + (size_t)(n0 + row) * DD + k0 + kg);
        r.bl[it] = *(const uint4*)(Bl + (size_t)(n0 + row) * DD + k0 + kg);
    }
}
__device__ __forceinline__ void sts_chunk(char* buf, int tid, const LdgRegs& r)
{
    #pragma unroll
    for (int it = 0; it < 2; it++) {
        int gid = tid + it * 256;
        int row = gid >> 2, kg = (gid & 3) << 3;
        uint32_t off = (uint32_t)(row * RSTR + kg) * 2;
        *(uint4*)(buf + OFF_AH + off) = r.ah[it];
        *(uint4*)(buf + OFF_AL + off) = r.al[it];
        *(uint4*)(buf + OFF_BH + off) = r.bh[it];
        *(uint4*)(buf + OFF_BL + off) = r.bl[it];
    }
}

__device__ __forceinline__ void gemm_loop(
    const __nv_bfloat16* __restrict__ Ah, const __nv_bfloat16* __restrict__ Al,
    const __nv_bfloat16* __restrict__ Bh, const __nv_bfloat16* __restrict__ Bl,
    int m0, int n0, char* sm, float acc[4][4][4])
{
    const int tid  = threadIdx.x;
    const int lane = tid & 31;
    const int warp = tid >> 5;
    const int wm   = warp & 1;
    const int wn   = warp >> 1;

    const uint32_t sb = s2u(sm);
    const int a_row = wm * 64 + (lane & 7) + ((lane >> 3) & 1) * 8;
    const int a_kof = (lane >> 4) * 8;
    const int b_row = wn * 32 + (lane & 7);
    const int b_kof = ((lane >> 3) & 1) * 8;

    LdgRegs r;
    ldg_chunk(Ah, Al, Bh, Bl, m0, n0, 0, tid, r);
    sts_chunk(sm, tid, r);
    __syncthreads();

    for (int c = 0; c < NCHUNK; c++) {
        if (c + 1 < NCHUNK)
            ldg_chunk(Ah, Al, Bh, Bl, m0, n0, (c + 1) * KCH, tid, r);

        const uint32_t bufb = sb + (uint32_t)(c & 1) * BUF_B;
        #pragma unroll
        for (int ks = 0; ks < 2; ks++) {
            uint32_t fah[4][4], fal[4][4], fbh[4][2], fbl[4][2];
            #pragma unroll
            for (int mi = 0; mi < 4; mi++) {
                uint32_t ao = bufb + (uint32_t)(((a_row + mi * 16) * RSTR) + ks * 16 + a_kof) * 2;
                ldsm4(fah[mi], ao + OFF_AH);
                ldsm4(fal[mi], ao + OFF_AL);
            }
            #pragma unroll
            for (int ni = 0; ni < 4; ni++) {
                uint32_t bo = bufb + (uint32_t)(((b_row + ni * 8) * RSTR) + ks * 16 + b_kof) * 2;
                ldsm2(fbh[ni], bo + OFF_BH);
                ldsm2(fbl[ni], bo + OFF_BL);
            }
            #pragma unroll
            for (int mi = 0; mi < 4; mi++)
                #pragma unroll
                for (int ni = 0; ni < 4; ni++) {
                    mma_bf16(acc[mi][ni], fah[mi], fbh[ni]);
                    mma_bf16(acc[mi][ni], fah[mi], fbl[ni]);
                    mma_bf16(acc[mi][ni], fal[mi], fbh[ni]);
                }
        }
        if (c + 1 < NCHUNK) {
            sts_chunk(sm + ((c + 1) & 1) * BUF_B, tid, r);
            __syncthreads();
        }
    }
}

// ---------------- projection GEMMs (Q/K/V) -> bf16 hi/lo ----------------
__global__ __launch_bounds__(256, 1) void proj_tc(const float* __restrict__ bq,
                                                  const float* __restrict__ bk,
                                                  const float* __restrict__ bv)
{
    extern __shared__ char sm[];
    const int z = blockIdx.z;
    const __nv_bfloat16* Bh = (z == 0) ? g_WqTh : (z == 1) ? g_WkTh : g_WvTh;
    const __nv_bfloat16* Bl = (z == 0) ? g_WqTl : (z == 1) ? g_WkTl : g_WvTl;
    const float* bias       = (z == 0) ? bq : (z == 1) ? bk : bv;
    __nv_bfloat16* Oh       = (z == 0) ? g_Qh : (z == 1) ? g_Kh : g_Vh;
    __nv_bfloat16* Ol       = (z == 0) ? g_Ql : (z == 1) ? g_Kl : g_Vl;

    const int m0 = blockIdx.y * 128;
    const int n0 = blockIdx.x * 128;

    float acc[4][4][4];
    #pragma unroll
    for (int mi = 0; mi < 4; mi++)
        #pragma unroll
        for (int ni = 0; ni < 4; ni++)
            #pragma unroll
            for (int k = 0; k < 4; k++) acc[mi][ni][k] = 0.f;

    gemm_loop(g_xh, g_xl, Bh, Bl, m0, n0, sm, acc);

    const int lane = threadIdx.x & 31;
    const int warp = threadIdx.x >> 5;
    const int wm = warp & 1, wn = warp >> 1;

    #pragma unroll
    for (int ni = 0; ni < 4; ni++) {
        const int gn = n0 + wn * 32 + ni * 8 + (lane & 3) * 2;
        const int h = gn >> 6, dh = gn & 63;
        const float b0 = bias[gn], b1 = bias[gn + 1];
        #pragma unroll
        for (int mi = 0; mi < 4; mi++) {
            const int gm = m0 + wm * 64 + mi * 16 + (lane >> 2);
            #pragma unroll
            for (int rh = 0; rh < 2; rh++) {
                const int m = gm + rh * 8;
                const int bidx = m >> 11, s = m & 2047;
                float vx = acc[mi][ni][rh * 2 + 0] + b0;
                float vy = acc[mi][ni][rh * 2 + 1] + b1;
                uint32_t uh, ul;
                split2(vx, vy, uh, ul);
                size_t idx = (((size_t)bidx * HH + h) * SS + s) * DHH + dh;
                *(uint32_t*)(Oh + idx) = uh;
                *(uint32_t*)(Ol + idx) = ul;
            }
        }
    }
}

// ---------------- output projection ----------------
__global__ __launch_bounds__(256, 1) void outproj_tc(const float* __restrict__ bo,
                                                     float* __restrict__ out)
{
    extern __shared__ char sm[];
    const int m0 = blockIdx.y * 128;
    const int n0 = blockIdx.x * 128;

    float acc[4][4][4];
    #pragma unroll
    for (int mi = 0; mi < 4; mi++)
        #pragma unroll
        for (int ni = 0; ni < 4; ni++)
            #pragma unroll
            for (int k = 0; k < 4; k++) acc[mi][ni][k] = 0.f;

    gemm_loop(g_Oh, g_Ol, g_WoTh, g_WoTl, m0, n0, sm, acc);

    const int lane = threadIdx.x & 31;
    const int warp = threadIdx.x >> 5;
    const int wm = warp & 1, wn = warp >> 1;

    #pragma unroll
    for (int ni = 0; ni < 4; ni++) {
        const int gn = n0 + wn * 32 + ni * 8 + (lane & 3) * 2;
        const float b0 = bo[gn], b1 = bo[gn + 1];
        #pragma unroll
        for (int mi = 0; mi < 4; mi++) {
            const int gm = m0 + wm * 64 + mi * 16 + (lane >> 2);
            #pragma unroll
            for (int rh = 0; rh < 2; rh++) {
                const int m = gm + rh * 8;
                float2 v;
                v.x = acc[mi][ni][rh * 2 + 0] + b0;
                v.y = acc[mi][ni][rh * 2 + 1] + b1;
                *(float2*)(out + (size_t)m * DD + gn) = v;
            }
        }
    }
}

// ---------------- tensor-core attention, faithful recurrence ----------------
// Block: 64 q-rows x (b,h). 4 warps; warp w owns q rows w*16..+15, all N.
// Smem (bytes): Qh@0, Ql@9216; KV double-buffer @18432: per buf {Kh,Kl,Vh,Vl}.
#define TSTR_B   144                  // 72 bf16 per row
#define TILE_KV  (64 * TSTR_B)        // 9216
#define KVOFF    (2 * TILE_KV)        // 18432
#define KVBUF_B  (4 * TILE_KV)        // 36864
#define ATT_SMEM (KVOFF + 2 * KVBUF_B) // 92160

__global__ __launch_bounds__(128) void attn_tc()
{
    extern __shared__ char sm[];
    const int qt = blockIdx.x;
    const int q0 = qt * 64;
    const int bh = blockIdx.y;
    const size_t base = (size_t)bh * SS * DHH;
    const __nv_bfloat16* __restrict__ Qh = g_Qh + base;
    const __nv_bfloat16* __restrict__ Ql = g_Ql + base;
    const __nv_bfloat16* __restrict__ Kh = g_Kh + base;
    const __nv_bfloat16* __restrict__ Kl = g_Kl + base;
    const __nv_bfloat16* __restrict__ Vh = g_Vh + base;
    const __nv_bfloat16* __restrict__ Vl = g_Vl + base;

    const int tid  = threadIdx.x;
    const int lane = tid & 31;
    const int warp = tid >> 5;
    const uint32_t smb = s2u(sm);

    // ---- load Q tile (hi/lo) into smem ----
    #pragma unroll
    for (int it = 0; it < 4; it++) {
        int s = it * 128 + tid;
        int row = s >> 3, seg = s & 7;
        *(uint4*)(sm + row * TSTR_B + seg * 16) =
            *(const uint4*)(Qh + (size_t)(q0 + row) * DHH + seg * 8);
        *(uint4*)(sm + TILE_KV + row * TSTR_B + seg * 16) =
            *(const uint4*)(Ql + (size_t)(q0 + row) * DHH + seg * 8);
    }
    __syncthreads();

    // ---- Q fragments (persistent) ----
    uint32_t qfh[4][4], qfl[4][4];
    {
        uint32_t qa = smb + (uint32_t)((warp * 16 + (lane & 7) + ((lane >> 3) & 1) * 8) * TSTR_B
                                       + ((lane >> 4) & 1) * 16);
        #pragma unroll
        for (int ks = 0; ks < 4; ks++) {
            ldsm4(qfh[ks], qa + ks * 32);
            ldsm4(qfl[ks], qa + ks * 32 + TILE_KV);
        }
    }

    float o[8][4];
    #pragma unroll
    for (int nb = 0; nb < 8; nb++)
        #pragma unroll
        for (int r = 0; r < 4; r++) o[nb][r] = 0.f;
    float m0s = -CUDART_INF_F, m1s = -CUDART_INF_F, l0s = 0.f, l1s = 0.f;

    const int qlo = q0 + warp * 16 + (lane >> 2);
    const int qhi = qlo + 8;

    // ---- cp.async K/V tile issue ----
    auto issue_kv = [&](int j, int buf) {
        uint32_t dstb = smb + KVOFF + (uint32_t)buf * KVBUF_B;
        const __nv_bfloat16* srcs[4] = {Kh, Kl, Vh, Vl};
        #pragma unroll
        for (int t = 0; t < 4; t++) {
            #pragma unroll
            for (int it = 0; it < 4; it++) {
                int s = it * 128 + tid;
                int row = s >> 3, seg = s & 7;
                cpa16(dstb + (uint32_t)(t * TILE_KV + row * TSTR_B + seg * 16),
                      srcs[t] + (size_t)(j * 64 + row) * DHH + seg * 8);
            }
        }
        CPA_COMMIT();
    };

    issue_kv(0, 0);

    for (int j = 0; j <= qt; j++) {
        if (j < qt) { issue_kv(j + 1, (j + 1) & 1); CPA_WAIT(1); }
        else        { CPA_WAIT(0); }
        __syncthreads();

        const uint32_t kb = smb + KVOFF + (uint32_t)(j & 1) * KVBUF_B;

        // ---- S = Q K^T (bf16x3) ----
        float c[8][4];
        #pragma unroll
        for (int nb = 0; nb < 8; nb++)
            #pragma unroll
            for (int r = 0; r < 4; r++) c[nb][r] = 0.f;

        #pragma unroll
        for (int ks = 0; ks < 4; ks++) {
            uint32_t kfh[4][4], kfl[4][4];
            #pragma unroll
            for (int p = 0; p < 4; p++) {
                uint32_t ka = kb + (uint32_t)((p * 16 + (lane & 7) + ((lane >> 4) & 1) * 8) * TSTR_B
                                              + ((lane >> 3) & 1) * 16 + ks * 32);
                ldsm4(kfh[p], ka);
                ldsm4(kfl[p], ka + TILE_KV);
            }
            #pragma unroll
            for (int p = 0; p < 4; p++)
                #pragma unroll
                for (int h2 = 0; h2 < 2; h2++) {
                    int nb = p * 2 + h2;
                    mma_bf16(c[nb], qfh[ks], &kfh[p][h2 * 2]);
                    mma_bf16(c[nb], qfh[ks], &kfl[p][h2 * 2]);
                    mma_bf16(c[nb], qfl[ks], &kfh[p][h2 * 2]);
                }
        }

        // ---- softmax recurrence (exact reference math) ----
        const bool diag = (j == qt);
        float mx0 = -CUDART_INF_F, mx1 = -CUDART_INF_F;
        #pragma unroll
        for (int nb = 0; nb < 8; nb++) {
            #pragma unroll
            for (int r = 0; r < 4; r++) c[nb][r] *= 0.125f;
            if (diag) {
                int colb = j * 64 + nb * 8 + (lane & 3) * 2;
                if (colb     > qlo) c[nb][0] = -CUDART_INF_F;
                if (colb + 1 > qlo) c[nb][1] = -CUDART_INF_F;
                if (colb     > qhi) c[nb][2] = -CUDART_INF_F;
                if (colb + 1 > qhi) c[nb][3] = -CUDART_INF_F;
            }
            mx0 = fmaxf(mx0, fmaxf(c[nb][0], c[nb][1]));
            mx1 = fmaxf(mx1, fmaxf(c[nb][2], c[nb][3]));
        }
        mx0 = fmaxf(mx0, __shfl_xor_sync(0xffffffffu, mx0, 1));
        mx0 = fmaxf(mx0, __shfl_xor_sync(0xffffffffu, mx0, 2));
        mx1 = fmaxf(mx1, __shfl_xor_sync(0xffffffffu, mx1, 1));
        mx1 = fmaxf(mx1, __shfl_xor_sync(0xffffffffu, mx1, 2));

        const float mn0 = fmaxf(m0s, mx0), mn1 = fmaxf(m1s, mx1);
        float s0 = 0.f, s1 = 0.f;
        #pragma unroll
        for (int nb = 0; nb < 8; nb++) {
            c[nb][0] = __expf(c[nb][0] - mn0);
            c[nb][1] = __expf(c[nb][1] - mn0);
            c[nb][2] = __expf(c[nb][2] - mn1);
            c[nb][3] = __expf(c[nb][3] - mn1);
            s0 += c[nb][0] + c[nb][1];
            s1 += c[nb][2] + c[nb][3];
        }
        s0 += __shfl_xor_sync(0xffffffffu, s0, 1);
        s0 += __shfl_xor_sync(0xffffffffu, s0, 2);
        s1 += __shfl_xor_sync(0xffffffffu, s1, 1);
        s1 += __shfl_xor_sync(0xffffffffu, s1, 2);

        const float a0 = __expf(m0s - mn0), a1 = __expf(m1s - mn1);
        const float ln0 = a0 * l0s + s0, ln1 = a1 * l1s + s1;
        const float f0 = l0s / ln0 * a0, f1 = l1s / ln1 * a1;
        #pragma unroll
        for (int nb = 0; nb < 8; nb++) {
            o[nb][0] *= f0; o[nb][1] *= f0;
            o[nb][2] *= f1; o[nb][3] *= f1;
        }
        m0s = mn0; l0s = ln0; m1s = mn1; l1s = ln1;

        // ---- O += P @ V (bf16x3; P from registers) ----
        const uint32_t vbh = kb + 2 * TILE_KV;
        #pragma unroll
        for (int ks = 0; ks < 4; ks++) {
            uint32_t pah[4], pal[4];
            split2(c[2 * ks][0],     c[2 * ks][1],     pah[0], pal[0]);
            split2(c[2 * ks][2],     c[2 * ks][3],     pah[1], pal[1]);
            split2(c[2 * ks + 1][0], c[2 * ks + 1][1], pah[2], pal[2]);
            split2(c[2 * ks + 1][2], c[2 * ks + 1][3], pah[3], pal[3]);

            uint32_t vfh[4][4], vfl[4][4];
            #pragma unroll
            for (int p = 0; p < 4; p++) {
                uint32_t va = vbh + (uint32_t)((ks * 16 + (lane & 7) + ((lane >> 3) & 1) * 8) * TSTR_B
                                               + (p * 16 + ((lane >> 4) & 1) * 8) * 2);
                ldsm4t(vfh[p], va);
                ldsm4t(vfl[p], va + TILE_KV);
            }
            #pragma unroll
            for (int p = 0; p < 4; p++)
                #pragma unroll
                for (int h2 = 0; h2 < 2; h2++) {
                    int nb = p * 2 + h2;
                    mma_bf16(o[nb], pah, &vfh[p][h2 * 2]);
                    mma_bf16(o[nb], pah, &vfl[p][h2 * 2]);
                    mma_bf16(o[nb], pal, &vfh[p][h2 * 2]);
                }
        }
        __syncthreads();
    }

    // ---- write O as bf16 hi/lo, (B,S,D) ----
    const int b = bh >> 4, hq = bh & 15;
    #pragma unroll
    for (int nb = 0; nb < 8; nb++) {
        const int col = hq * 64 + nb * 8 + (lane & 3) * 2;
        uint32_t ph, pl;
        split2(o[nb][0], o[nb][1], ph, pl);
        size_t idx = ((size_t)b * SS + qlo) * DD + col;
        *(uint32_t*)(g_Oh + idx) = ph;
        *(uint32_t*)(g_Ol + idx) = pl;
        split2(o[nb][2], o[nb][3], ph, pl);
        idx = ((size_t)b * SS + qhi) * DD + col;
        *(uint32_t*)(g_Oh + idx) = ph;
        *(uint32_t*)(g_Ol + idx) = pl;
    }
}

// ---------------- launch ----------------
extern "C" void kernel_launch(void* const* d_in, const int* in_sizes, int n_in,
                              void* d_out, int out_size)
{
    const float* x  = (const float*)d_in[0];
    const float* Wq = (const float*)d_in[1];
    const float* bq = (const float*)d_in[2];
    const float* Wk = (const float*)d_in[3];
    const float* bk = (const float*)d_in[4];
    const float* Wv = (const float*)d_in[5];
    const float* bv = (const float*)d_in[6];
    const float* Wo = (const float*)d_in[7];
    const float* bo = (const float*)d_in[8];
    float* out = (float*)d_out;

    static bool attr_done = false;
    if (!attr_done) {
        cudaFuncSetAttribute(attn_tc,
                             cudaFuncAttributeMaxDynamicSharedMemorySize, ATT_SMEM);
        cudaFuncSetAttribute(proj_tc,
                             cudaFuncAttributeMaxDynamicSharedMemorySize, GEMM_SMEM);
        cudaFuncSetAttribute(outproj_tc,
                             cudaFuncAttributeMaxDynamicSharedMemorySize, GEMM_SMEM);
        attr_done = true;
    }

    split_x<<<(BB * SS * DD) / (256 * 4), 256>>>(x);
    transpose_split<<<dim3(DD / 32, DD / 32, 4), dim3(32, 8)>>>(Wq, Wk, Wv, Wo);
    proj_tc<<<dim3(DD / 128, (BB * SS) / 128, 3), 256, GEMM_SMEM>>>(bq, bk, bv);
    attn_tc<<<dim3(SS / 64, BB * HH), 128, ATT_SMEM>>>();
    outproj_tc<<<dim3(DD / 128, (BB * SS) / 128), 256, GEMM_SMEM>>>(bo, out);
}

// round 8
// speedup vs baseline: 2.8593x; 1.1069x over previous
#include <cuda_runtime.h>
#include <cuda_bf16.h>
#include <math_constants.h>
#include <cstdint>

#define BB  4
#define SS  2048
#define DD  1024
#define HH  16
#define DHH 64

// ---------------- scratch (device globals; no allocations) ----------------
__device__ __nv_bfloat16 g_xh[(size_t)BB * SS * DD];
__device__ __nv_bfloat16 g_xl[(size_t)BB * SS * DD];
__device__ __nv_bfloat16 g_WqTh[(size_t)DD * DD], g_WqTl[(size_t)DD * DD];
__device__ __nv_bfloat16 g_WkTh[(size_t)DD * DD], g_WkTl[(size_t)DD * DD];
__device__ __nv_bfloat16 g_WvTh[(size_t)DD * DD], g_WvTl[(size_t)DD * DD];
__device__ __nv_bfloat16 g_WoTh[(size_t)DD * DD], g_WoTl[(size_t)DD * DD];
__device__ __nv_bfloat16 g_Qh[(size_t)BB * HH * SS * DHH], g_Ql[(size_t)BB * HH * SS * DHH];
__device__ __nv_bfloat16 g_Kh[(size_t)BB * HH * SS * DHH], g_Kl[(size_t)BB * HH * SS * DHH];
__device__ __nv_bfloat16 g_Vh[(size_t)BB * HH * SS * DHH], g_Vl[(size_t)BB * HH * SS * DHH];
__device__ __nv_bfloat16 g_Oh[(size_t)BB * SS * DD];
__device__ __nv_bfloat16 g_Ol[(size_t)BB * SS * DD];

// ---------------- PTX helpers (sm_80+ only) ----------------
__device__ __forceinline__ uint32_t s2u(const void* p) {
    uint32_t a;
    asm("{ .reg .u64 t; cvta.to.shared.u64 t, %1; cvt.u32.u64 %0, t; }"
        : "=r"(a) : "l"(p));
    return a;
}
__device__ __forceinline__ void ldsm4(uint32_t* r, uint32_t addr) {
    asm volatile("ldmatrix.sync.aligned.m8n8.x4.shared.b16 {%0,%1,%2,%3}, [%4];"
        : "=r"(r[0]), "=r"(r[1]), "=r"(r[2]), "=r"(r[3]) : "r"(addr));
}
__device__ __forceinline__ void ldsm4t(uint32_t* r, uint32_t addr) {
    asm volatile("ldmatrix.sync.aligned.m8n8.x4.trans.shared.b16 {%0,%1,%2,%3}, [%4];"
        : "=r"(r[0]), "=r"(r[1]), "=r"(r[2]), "=r"(r[3]) : "r"(addr));
}
__device__ __forceinline__ void ldsm2(uint32_t* r, uint32_t addr) {
    asm volatile("ldmatrix.sync.aligned.m8n8.x2.shared.b16 {%0,%1}, [%2];"
        : "=r"(r[0]), "=r"(r[1]) : "r"(addr));
}
__device__ __forceinline__ void mma_bf16(float* d, const uint32_t* a, const uint32_t* b) {
    asm volatile(
        "mma.sync.aligned.m16n8k16.row.col.f32.bf16.bf16.f32 "
        "{%0,%1,%2,%3}, {%4,%5,%6,%7}, {%8,%9}, {%0,%1,%2,%3};"
        : "+f"(d[0]), "+f"(d[1]), "+f"(d[2]), "+f"(d[3])
        : "r"(a[0]), "r"(a[1]), "r"(a[2]), "r"(a[3]), "r"(b[0]), "r"(b[1]));
}
__device__ __forceinline__ void cpa16(uint32_t s, const void* g) {
    asm volatile("cp.async.cg.shared.global [%0], [%1], 16;" :: "r"(s), "l"(g));
}
#define CPA_COMMIT() asm volatile("cp.async.commit_group;" ::: "memory")
#define CPA_WAIT(n)  asm volatile("cp.async.wait_group %0;" :: "n"(n) : "memory")

__device__ __forceinline__ uint32_t packbf(float x, float y) {
    __nv_bfloat162 t = __floats2bfloat162_rn(x, y);
    return *(uint32_t*)&t;
}
__device__ __forceinline__ void split2(float a, float b, uint32_t& h, uint32_t& l) {
    float ha = __bfloat162float(__float2bfloat16(a));
    float hb = __bfloat162float(__float2bfloat16(b));
    h = packbf(ha, hb);
    l = packbf(a - ha, b - hb);
}

// ---------------- bf16 hi/lo split kernels ----------------
__global__ __launch_bounds__(256) void split_x(const float* __restrict__ x) {
    size_t i = ((size_t)blockIdx.x * 256 + threadIdx.x) * 4;
    float4 v = *(const float4*)(x + i);
    float vv[4] = {v.x, v.y, v.z, v.w};
    __nv_bfloat16 h[4], l[4];
    #pragma unroll
    for (int j = 0; j < 4; j++) {
        h[j] = __float2bfloat16(vv[j]);
        l[j] = __float2bfloat16(vv[j] - __bfloat162float(h[j]));
    }
    *(uint2*)(g_xh + i) = *(uint2*)h;
    *(uint2*)(g_xl + i) = *(uint2*)l;
}

__global__ void transpose_split(const float* __restrict__ Wq, const float* __restrict__ Wk,
                                const float* __restrict__ Wv, const float* __restrict__ Wo) {
    __shared__ float t[32][33];
    const int z = blockIdx.z;
    const float* W = (z == 0) ? Wq : (z == 1) ? Wk : (z == 2) ? Wv : Wo;
    __nv_bfloat16* Th = (z == 0) ? g_WqTh : (z == 1) ? g_WkTh : (z == 2) ? g_WvTh : g_WoTh;
    __nv_bfloat16* Tl = (z == 0) ? g_WqTl : (z == 1) ? g_WkTl : (z == 2) ? g_WvTl : g_WoTl;
    const int n0 = blockIdx.x * 32, k0 = blockIdx.y * 32;
    const int tx = threadIdx.x, ty = threadIdx.y;
    #pragma unroll
    for (int j = 0; j < 32; j += 8)
        t[ty + j][tx] = W[(size_t)(k0 + ty + j) * DD + n0 + tx];
    __syncthreads();
    #pragma unroll
    for (int j = 0; j < 32; j += 8) {
        float v = t[tx][ty + j];
        int n = n0 + ty + j, k = k0 + tx;
        __nv_bfloat16 h = __float2bfloat16(v);
        __nv_bfloat16 l = __float2bfloat16(v - __bfloat162float(h));
        Th[(size_t)n * DD + k] = h;
        Tl[(size_t)n * DD + k] = l;
    }
}

// ---------------- mma.sync GEMM: 128x128 tile, bf16x3, cp.async ------------
#define KCH     32
#define NCHUNK  (DD / KCH)
#define RSTR    40
#define TILE_B  (128 * RSTR * 2)
#define BUF_B   (4 * TILE_B)
#define GEMM_SMEM (2 * BUF_B)

__device__ __forceinline__ void gemm_loop(
    const __nv_bfloat16* __restrict__ Ah, const __nv_bfloat16* __restrict__ Al,
    const __nv_bfloat16* __restrict__ Bh, const __nv_bfloat16* __restrict__ Bl,
    int m0, int n0, char* sm, float acc[4][4][4])
{
    const int tid  = threadIdx.x;
    const int lane = tid & 31;
    const int warp = tid >> 5;
    const int wm   = warp & 1;
    const int wn   = warp >> 1;

    const uint32_t sb = s2u(sm);
    const int a_row = wm * 64 + (lane & 7) + ((lane >> 3) & 1) * 8;
    const int a_kof = (lane >> 4) * 8;
    const int b_row = wn * 32 + (lane & 7);
    const int b_kof = ((lane >> 3) & 1) * 8;

    auto issue = [&](int k0, uint32_t dstb) {
        #pragma unroll
        for (int it = 0; it < 8; it++) {
            int gid  = it * 256 + tid;       // 0..2047
            int tile = gid >> 9;             // 0..3
            int row  = (gid >> 2) & 127;
            int seg  = gid & 3;
            const __nv_bfloat16* src = (tile == 0) ? Ah : (tile == 1) ? Al
                                     : (tile == 2) ? Bh : Bl;
            int rb = (tile < 2) ? m0 : n0;
            cpa16(dstb + (uint32_t)tile * TILE_B + (uint32_t)(row * RSTR + seg * 8) * 2,
                  src + (size_t)(rb + row) * DD + k0 + seg * 8);
        }
        CPA_COMMIT();
    };

    issue(0, sb);

    for (int c = 0; c < NCHUNK; c++) {
        CPA_WAIT(0);
        __syncthreads();
        const uint32_t bufb = sb + (uint32_t)(c & 1) * BUF_B;
        #pragma unroll
        for (int ks = 0; ks < 2; ks++) {
            uint32_t fbh[4][2], fbl[4][2];
            #pragma unroll
            for (int ni = 0; ni < 4; ni++) {
                uint32_t bo = bufb + (uint32_t)(((b_row + ni * 8) * RSTR) + ks * 16 + b_kof) * 2;
                ldsm2(fbh[ni], bo + 2 * TILE_B);
                ldsm2(fbl[ni], bo + 3 * TILE_B);
            }
            #pragma unroll
            for (int mi = 0; mi < 4; mi++) {
                uint32_t fah[4], fal[4];
                uint32_t ao = bufb + (uint32_t)(((a_row + mi * 16) * RSTR) + ks * 16 + a_kof) * 2;
                ldsm4(fah, ao);
                ldsm4(fal, ao + TILE_B);
                #pragma unroll
                for (int ni = 0; ni < 4; ni++) {
                    mma_bf16(acc[mi][ni], fah, fbh[ni]);
                    mma_bf16(acc[mi][ni], fah, fbl[ni]);
                    mma_bf16(acc[mi][ni], fal, fbh[ni]);
                }
            }
        }
        if (c + 1 < NCHUNK)
            issue((c + 1) * KCH, sb + (uint32_t)((c + 1) & 1) * BUF_B);
    }
}

// ---------------- projection GEMMs (Q/K/V) -> bf16 hi/lo ----------------
__global__ __launch_bounds__(256, 2) void proj_tc(const float* __restrict__ bq,
                                                  const float* __restrict__ bk,
                                                  const float* __restrict__ bv)
{
    extern __shared__ char sm[];
    const int z = blockIdx.z;
    const __nv_bfloat16* Bh = (z == 0) ? g_WqTh : (z == 1) ? g_WkTh : g_WvTh;
    const __nv_bfloat16* Bl = (z == 0) ? g_WqTl : (z == 1) ? g_WkTl : g_WvTl;
    const float* bias       = (z == 0) ? bq : (z == 1) ? bk : bv;
    __nv_bfloat16* Oh       = (z == 0) ? g_Qh : (z == 1) ? g_Kh : g_Vh;
    __nv_bfloat16* Ol       = (z == 0) ? g_Ql : (z == 1) ? g_Kl : g_Vl;

    const int m0 = blockIdx.y * 128;
    const int n0 = blockIdx.x * 128;

    float acc[4][4][4];
    #pragma unroll
    for (int mi = 0; mi < 4; mi++)
        #pragma unroll
        for (int ni = 0; ni < 4; ni++)
            #pragma unroll
            for (int k = 0; k < 4; k++) acc[mi][ni][k] = 0.f;

    gemm_loop(g_xh, g_xl, Bh, Bl, m0, n0, sm, acc);

    const int lane = threadIdx.x & 31;
    const int warp = threadIdx.x >> 5;
    const int wm = warp & 1, wn = warp >> 1;

    #pragma unroll
    for (int ni = 0; ni < 4; ni++) {
        const int gn = n0 + wn * 32 + ni * 8 + (lane & 3) * 2;
        const int h = gn >> 6, dh = gn & 63;
        const float b0 = bias[gn], b1 = bias[gn + 1];
        #pragma unroll
        for (int mi = 0; mi < 4; mi++) {
            const int gm = m0 + wm * 64 + mi * 16 + (lane >> 2);
            #pragma unroll
            for (int rh = 0; rh < 2; rh++) {
                const int m = gm + rh * 8;
                const int bidx = m >> 11, s = m & 2047;
                float vx = acc[mi][ni][rh * 2 + 0] + b0;
                float vy = acc[mi][ni][rh * 2 + 1] + b1;
                uint32_t uh, ul;
                split2(vx, vy, uh, ul);
                size_t idx = (((size_t)bidx * HH + h) * SS + s) * DHH + dh;
                *(uint32_t*)(Oh + idx) = uh;
                *(uint32_t*)(Ol + idx) = ul;
            }
        }
    }
}

// ---------------- output projection ----------------
__global__ __launch_bounds__(256, 2) void outproj_tc(const float* __restrict__ bo,
                                                     float* __restrict__ out)
{
    extern __shared__ char sm[];
    const int m0 = blockIdx.y * 128;
    const int n0 = blockIdx.x * 128;

    float acc[4][4][4];
    #pragma unroll
    for (int mi = 0; mi < 4; mi++)
        #pragma unroll
        for (int ni = 0; ni < 4; ni++)
            #pragma unroll
            for (int k = 0; k < 4; k++) acc[mi][ni][k] = 0.f;

    gemm_loop(g_Oh, g_Ol, g_WoTh, g_WoTl, m0, n0, sm, acc);

    const int lane = threadIdx.x & 31;
    const int warp = threadIdx.x >> 5;
    const int wm = warp & 1, wn = warp >> 1;

    #pragma unroll
    for (int ni = 0; ni < 4; ni++) {
        const int gn = n0 + wn * 32 + ni * 8 + (lane & 3) * 2;
        const float b0 = bo[gn], b1 = bo[gn + 1];
        #pragma unroll
        for (int mi = 0; mi < 4; mi++) {
            const int gm = m0 + wm * 64 + mi * 16 + (lane >> 2);
            #pragma unroll
            for (int rh = 0; rh < 2; rh++) {
                const int m = gm + rh * 8;
                float2 v;
                v.x = acc[mi][ni][rh * 2 + 0] + b0;
                v.y = acc[mi][ni][rh * 2 + 1] + b1;
                *(float2*)(out + (size_t)m * DD + gn) = v;
            }
        }
    }
}

// ---------------- tensor-core attention, faithful recurrence ----------------
// 64 q-rows x (b,h); 4 warps. Single K buffer + single V buffer, ping-ponged
// as separate cp.async groups: K(j+1) loads during PV(j), V(j+1) during S(j+1).
// Smem: Qh,Ql,Kh,Kl,Vh,Vl tiles of 9216B each = 55296B -> 3 CTAs/SM.
#define TSTR_B   144
#define TILE_KV  (64 * TSTR_B)        // 9216
#define OFF_KH   (2 * TILE_KV)
#define OFF_VH   (4 * TILE_KV)
#define ATT_SMEM (6 * TILE_KV)        // 55296

__global__ __launch_bounds__(128, 3) void attn_tc()
{
    extern __shared__ char sm[];
    const int qt = blockIdx.x;
    const int q0 = qt * 64;
    const int bh = blockIdx.y;
    const size_t base = (size_t)bh * SS * DHH;
    const __nv_bfloat16* __restrict__ Qh = g_Qh + base;
    const __nv_bfloat16* __restrict__ Ql = g_Ql + base;
    const __nv_bfloat16* __restrict__ Kh = g_Kh + base;
    const __nv_bfloat16* __restrict__ Kl = g_Kl + base;
    const __nv_bfloat16* __restrict__ Vh = g_Vh + base;
    const __nv_bfloat16* __restrict__ Vl = g_Vl + base;

    const int tid  = threadIdx.x;
    const int lane = tid & 31;
    const int warp = tid >> 5;
    const uint32_t smb = s2u(sm);

    // issue one (hi,lo) tile pair as a single commit group
    auto issue_pair = [&](const __nv_bfloat16* Sh, const __nv_bfloat16* Sl,
                          uint32_t dstb, int j) {
        #pragma unroll
        for (int it = 0; it < 8; it++) {
            int s = it * 128 + tid;          // 0..1023
            int half = s >> 9;               // 0=hi,1=lo
            int row = (s >> 3) & 63;
            int seg = s & 7;
            cpa16(dstb + (uint32_t)half * TILE_KV + (uint32_t)(row * TSTR_B + seg * 16),
                  (half ? Sl : Sh) + (size_t)(j * 64 + row) * DHH + seg * 8);
        }
        CPA_COMMIT();
    };

    // ---- load Q tile (hi/lo) into smem + start K(0),V(0) ----
    #pragma unroll
    for (int it = 0; it < 4; it++) {
        int s = it * 128 + tid;
        int row = s >> 3, seg = s & 7;
        *(uint4*)(sm + row * TSTR_B + seg * 16) =
            *(const uint4*)(Qh + (size_t)(q0 + row) * DHH + seg * 8);
        *(uint4*)(sm + TILE_KV + row * TSTR_B + seg * 16) =
            *(const uint4*)(Ql + (size_t)(q0 + row) * DHH + seg * 8);
    }
    issue_pair(Kh, Kl, smb + OFF_KH, 0);
    issue_pair(Vh, Vl, smb + OFF_VH, 0);
    __syncthreads();

    // ---- Q fragments (persistent) ----
    uint32_t qfh[4][4], qfl[4][4];
    {
        uint32_t qa = smb + (uint32_t)((warp * 16 + (lane & 7) + ((lane >> 3) & 1) * 8) * TSTR_B
                                       + ((lane >> 4) & 1) * 16);
        #pragma unroll
        for (int ks = 0; ks < 4; ks++) {
            ldsm4(qfh[ks], qa + ks * 32);
            ldsm4(qfl[ks], qa + ks * 32 + TILE_KV);
        }
    }

    float o[8][4];
    #pragma unroll
    for (int nb = 0; nb < 8; nb++)
        #pragma unroll
        for (int r = 0; r < 4; r++) o[nb][r] = 0.f;
    float m0s = -CUDART_INF_F, m1s = -CUDART_INF_F, l0s = 0.f, l1s = 0.f;

    const int qlo = q0 + warp * 16 + (lane >> 2);
    const int qhi = qlo + 8;

    for (int j = 0; j <= qt; j++) {
        // K(j) ready (V(j) may still be in flight)
        CPA_WAIT(1);
        __syncthreads();

        // ---- S = Q K^T (bf16x3) ----
        float c[8][4];
        #pragma unroll
        for (int nb = 0; nb < 8; nb++)
            #pragma unroll
            for (int r = 0; r < 4; r++) c[nb][r] = 0.f;

        #pragma unroll
        for (int ks = 0; ks < 4; ks++) {
            uint32_t kfh[4][4], kfl[4][4];
            #pragma unroll
            for (int p = 0; p < 4; p++) {
                uint32_t ka = smb + OFF_KH
                            + (uint32_t)((p * 16 + (lane & 7) + ((lane >> 4) & 1) * 8) * TSTR_B
                                         + ((lane >> 3) & 1) * 16 + ks * 32);
                ldsm4(kfh[p], ka);
                ldsm4(kfl[p], ka + TILE_KV);
            }
            #pragma unroll
            for (int p = 0; p < 4; p++)
                #pragma unroll
                for (int h2 = 0; h2 < 2; h2++) {
                    int nb = p * 2 + h2;
                    mma_bf16(c[nb], qfh[ks], &kfh[p][h2 * 2]);
                    mma_bf16(c[nb], qfh[ks], &kfl[p][h2 * 2]);
                    mma_bf16(c[nb], qfl[ks], &kfh[p][h2 * 2]);
                }
        }
        __syncthreads();                    // all warps done reading K
        if (j < qt) issue_pair(Kh, Kl, smb + OFF_KH, j + 1);

        // ---- softmax recurrence (exact reference math) ----
        const bool diag = (j == qt);
        float mx0 = -CUDART_INF_F, mx1 = -CUDART_INF_F;
        #pragma unroll
        for (int nb = 0; nb < 8; nb++) {
            #pragma unroll
            for (int r = 0; r < 4; r++) c[nb][r] *= 0.125f;
            if (diag) {
                int colb = j * 64 + nb * 8 + (lane & 3) * 2;
                if (colb     > qlo) c[nb][0] = -CUDART_INF_F;
                if (colb + 1 > qlo) c[nb][1] = -CUDART_INF_F;
                if (colb     > qhi) c[nb][2] = -CUDART_INF_F;
                if (colb + 1 > qhi) c[nb][3] = -CUDART_INF_F;
            }
            mx0 = fmaxf(mx0, fmaxf(c[nb][0], c[nb][1]));
            mx1 = fmaxf(mx1, fmaxf(c[nb][2], c[nb][3]));
        }
        mx0 = fmaxf(mx0, __shfl_xor_sync(0xffffffffu, mx0, 1));
        mx0 = fmaxf(mx0, __shfl_xor_sync(0xffffffffu, mx0, 2));
        mx1 = fmaxf(mx1, __shfl_xor_sync(0xffffffffu, mx1, 1));
        mx1 = fmaxf(mx1, __shfl_xor_sync(0xffffffffu, mx1, 2));

        const float mn0 = fmaxf(m0s, mx0), mn1 = fmaxf(m1s, mx1);
        float s0 = 0.f, s1 = 0.f;
        #pragma unroll
        for (int nb = 0; nb < 8; nb++) {
            c[nb][0] = __expf(c[nb][0] - mn0);
            c[nb][1] = __expf(c[nb][1] - mn0);
            c[nb][2] = __expf(c[nb][2] - mn1);
            c[nb][3] = __expf(c[nb][3] - mn1);
            s0 += c[nb][0] + c[nb][1];
            s1 += c[nb][2] + c[nb][3];
        }
        s0 += __shfl_xor_sync(0xffffffffu, s0, 1);
        s0 += __shfl_xor_sync(0xffffffffu, s0, 2);
        s1 += __shfl_xor_sync(0xffffffffu, s1, 1);
        s1 += __shfl_xor_sync(0xffffffffu, s1, 2);

        const float a0 = __expf(m0s - mn0), a1 = __expf(m1s - mn1);
        const float ln0 = a0 * l0s + s0, ln1 = a1 * l1s + s1;
        const float f0 = l0s / ln0 * a0, f1 = l1s / ln1 * a1;
        #pragma unroll
        for (int nb = 0; nb < 8; nb++) {
            o[nb][0] *= f0; o[nb][1] *= f0;
            o[nb][2] *= f1; o[nb][3] *= f1;
        }
        m0s = mn0; l0s = ln0; m1s = mn1; l1s = ln1;

        // V(j) ready
        if (j < qt) { CPA_WAIT(1); } else { CPA_WAIT(0); }
        __syncthreads();

        // ---- O += P @ V (bf16x3; P from registers) ----
        #pragma unroll
        for (int ks = 0; ks < 4; ks++) {
            uint32_t pah[4], pal[4];
            split2(c[2 * ks][0],     c[2 * ks][1],     pah[0], pal[0]);
            split2(c[2 * ks][2],     c[2 * ks][3],     pah[1], pal[1]);
            split2(c[2 * ks + 1][0], c[2 * ks + 1][1], pah[2], pal[2]);
            split2(c[2 * ks + 1][2], c[2 * ks + 1][3], pah[3], pal[3]);

            uint32_t vfh[4][4], vfl[4][4];
            #pragma unroll
            for (int p = 0; p < 4; p++) {
                uint32_t va = smb + OFF_VH
                            + (uint32_t)((ks * 16 + (lane & 7) + ((lane >> 3) & 1) * 8) * TSTR_B
                                         + (p * 16 + ((lane >> 4) & 1) * 8) * 2);
                ldsm4t(vfh[p], va);
                ldsm4t(vfl[p], va + TILE_KV);
            }
            #pragma unroll
            for (int p = 0; p < 4; p++)
                #pragma unroll
                for (int h2 = 0; h2 < 2; h2++) {
                    int nb = p * 2 + h2;
                    mma_bf16(o[nb], pah, &vfh[p][h2 * 2]);
                    mma_bf16(o[nb], pah, &vfl[p][h2 * 2]);
                    mma_bf16(o[nb], pal, &vfh[p][h2 * 2]);
                }
        }
        __syncthreads();                    // all warps done reading V
        if (j < qt) issue_pair(Vh, Vl, smb + OFF_VH, j + 1);
    }

    // ---- write O as bf16 hi/lo, (B,S,D) ----
    const int b = bh >> 4, hq = bh & 15;
    #pragma unroll
    for (int nb = 0; nb < 8; nb++) {
        const int col = hq * 64 + nb * 8 + (lane & 3) * 2;
        uint32_t ph, pl;
        split2(o[nb][0], o[nb][1], ph, pl);
        size_t idx = ((size_t)b * SS + qlo) * DD + col;
        *(uint32_t*)(g_Oh + idx) = ph;
        *(uint32_t*)(g_Ol + idx) = pl;
        split2(o[nb][2], o[nb][3], ph, pl);
        idx = ((size_t)b * SS + qhi) * DD + col;
        *(uint32_t*)(g_Oh + idx) = ph;
        *(uint32_t*)(g_Ol + idx) = pl;
    }
}

// ---------------- launch ----------------
extern "C" void kernel_launch(void* const* d_in, const int* in_sizes, int n_in,
                              void* d_out, int out_size)
{
    const float* x  = (const float*)d_in[0];
    const float* Wq = (const float*)d_in[1];
    const float* bq = (const float*)d_in[2];
    const float* Wk = (const float*)d_in[3];
    const float* bk = (const float*)d_in[4];
    const float* Wv = (const float*)d_in[5];
    const float* bv = (const float*)d_in[6];
    const float* Wo = (const float*)d_in[7];
    const float* bo = (const float*)d_in[8];
    float* out = (float*)d_out;

    static bool attr_done = false;
    if (!attr_done) {
        cudaFuncSetAttribute(attn_tc,
                             cudaFuncAttributeMaxDynamicSharedMemorySize, ATT_SMEM);
        cudaFuncSetAttribute(proj_tc,
                             cudaFuncAttributeMaxDynamicSharedMemorySize, GEMM_SMEM);
        cudaFuncSetAttribute(outproj_tc,
                             cudaFuncAttributeMaxDynamicSharedMemorySize, GEMM_SMEM);
        attr_done = true;
    }

    split_x<<<(BB * SS * DD) / (256 * 4), 256>>>(x);
    transpose_split<<<dim3(DD / 32, DD / 32, 4), dim3(32, 8)>>>(Wq, Wk, Wv, Wo);
    proj_tc<<<dim3(DD / 128, (BB * SS) / 128, 3), 256, GEMM_SMEM>>>(bq, bk, bv);
    attn_tc<<<dim3(SS / 64, BB * HH), 128, ATT_SMEM>>>();
    outproj_tc<<<dim3(DD / 128, (BB * SS) / 128), 256, GEMM_SMEM>>>(bo, out);
}